// round 10
// baseline (speedup 1.0000x reference)
#include <cuda_runtime.h>
#include <cuda_bf16.h>
#include <math.h>

// ============================================================================
// quantizer: out = center[argmin_m |x - center[m]|]  (== W_hard; reference's
// (W_hard - W_soft) + W_soft == W_hard up to 1 ulp).
//
// R10 = R9 (fused prep + exact branch-free 2-deep main loop) with the code
// path trimmed: cvt.rni.u16.f32 (saturating) replaces F2I+IMNMX, and the
// byte-LUT grows to the full u16 code space (64 KB dynamic shared; 2 CTA/SM
// -> 128 KB/SM, fits).
//   main per element: FFMA -> CVT.u16.sat -> LDS.U8 -> SHFL(cross,b) ->
//     cmp -> SHFL(center, b+(x>=thr)).  No branches, no votes, exact.
// ============================================================================

#define LUT_SIZE 65536

__device__ __forceinline__ unsigned qcode(float xv, float scale, float bias)
{
    float t = fmaf(xv, scale, bias);
    unsigned short c;
    asm("cvt.rni.u16.f32 %0, %1;" : "=h"(c) : "f"(t));  // saturates [0,65535]
    return (unsigned)c;
}

__device__ __forceinline__ float qone(float xv, float scale, float bias,
                                      const unsigned char* __restrict__ sblut,
                                      float crossv, float centv)
{
    int b = (int)sblut[qcode(xv, scale, bias)];
    float thr = __shfl_sync(0xffffffffu, crossv, b);
    int r = b + ((xv >= thr) ? 1 : 0);       // r <= 15 (cross[15] = +inf)
    return __shfl_sync(0xffffffffu, centv, r);
}

extern "C" __global__ void __launch_bounds__(1024, 2)
quant_fused_kernel(const float4* __restrict__ x,
                   const float* __restrict__ center,
                   float4* __restrict__ out, int n4)
{
    extern __shared__ unsigned char sblut[];    // 64 KB region-byte LUT
    __shared__ float s_c[16];                   // sorted centers
    __shared__ int   s_oi[16];                  // original idx (argmin tie rule)
    __shared__ float s_cross[16];               // exact crossovers, [15]=+inf
    __shared__ float s_scale, s_bias;

    const int tid  = threadIdx.x;
    const int lane = tid & 31;

    // ---- prep 1: rank-sort 16 centers (lanes 0..15 of warp 0) ----
    if (tid < 16) {
        float ci = center[tid];
        int rank = 0;
        #pragma unroll
        for (int j = 0; j < 16; j++) {
            float cj = __shfl_sync(0xffffu, ci, j);
            rank += (cj < ci || (cj == ci && j < tid)) ? 1 : 0;
        }
        s_c[rank]  = ci;
        s_oi[rank] = tid;
    }
    __syncthreads();

    // ---- prep 2: grid params + exact crossovers (15 parallel bisections) ----
    if (tid == 0) {
        float mid0  = 0.5f * (s_c[0]  + s_c[1]);
        float mid14 = 0.5f * (s_c[14] + s_c[15]);
        float span  = mid14 - mid0;
        if (!(span > 0.0f)) span = 1e-6f;
        float step = span / (float)(LUT_SIZE - 1600);  // 800-cell margins
        float lo   = mid0 - 800.0f * step;
        s_scale = 1.0f / step;
        s_bias  = -lo / step;
    }
    if (tid < 16) {
        float cv;
        if (tid < 15) {
            // exact fp32 flip point of the reference's argmin decision for
            // sorted pair (k,k+1): bracket [c_k, c_{k+1}], monotone predicate,
            // bisect to adjacent floats. cv = smallest x picking RIGHT center.
            float cl = s_c[tid], cr = s_c[tid + 1];
            int   ol = s_oi[tid], orr = s_oi[tid + 1];
            float a = cl, b = cr;
            for (int it = 0; it < 60; it++) {
                float m = 0.5f * (a + b);
                if (m <= a || m >= b) break;
                float dl = fabsf(m - cl), dr = fabsf(m - cr);
                bool pl = (dl < dr) || (dl == dr && ol < orr);
                if (pl) a = m; else b = m;
            }
            cv = b;
        } else {
            cv = __int_as_float(0x7f800000);  // +inf sentinel for region 15
        }
        s_cross[tid] = cv;
    }
    __syncthreads();

    // ---- prep 3: fill byte LUT (region index at the cell's lower edge) ----
    const float scale = s_scale, bias = s_bias;
    const float inv = 1.0f / scale;
    for (int i = tid; i < LUT_SIZE; i += 1024) {
        // conservative lower x-edge of code i (rn 0.5 + fma rounding margin)
        float xlo = ((float)i - 1.5f - bias) * inv;
        int b = 0;
        #pragma unroll
        for (int k = 0; k < 15; k++) b += (s_cross[k] <= xlo) ? 1 : 0;
        sblut[i] = (unsigned char)b;
    }

    const float crossv = s_cross[lane & 15];   // per-lane register tables
    const float centv  = s_c[lane & 15];
    __syncthreads();

    // ---- main loop: warp-uniform bounds, 2x float4 deep (fits 32 regs) ----
    const int stride = gridDim.x * blockDim.x;
    int i  = blockIdx.x * blockDim.x + tid;
    int wb = i - lane;                          // warp-uniform base index

    for (; wb + 31 + stride < n4; i += 2 * stride, wb += 2 * stride) {
        float4 a = x[i];
        float4 b = x[i + stride];
        float4 ra, rb;
        ra.x = qone(a.x, scale, bias, sblut, crossv, centv);
        ra.y = qone(a.y, scale, bias, sblut, crossv, centv);
        ra.z = qone(a.z, scale, bias, sblut, crossv, centv);
        ra.w = qone(a.w, scale, bias, sblut, crossv, centv);
        rb.x = qone(b.x, scale, bias, sblut, crossv, centv);
        rb.y = qone(b.y, scale, bias, sblut, crossv, centv);
        rb.z = qone(b.z, scale, bias, sblut, crossv, centv);
        rb.w = qone(b.w, scale, bias, sblut, crossv, centv);
        out[i]          = ra;
        out[i + stride] = rb;
    }
    // tail: full-warp shuffles, predicated LDG/STG only
    for (; wb < n4; i += stride, wb += stride) {
        const bool v = (i < n4);
        float4 a = v ? x[i] : make_float4(0.f, 0.f, 0.f, 0.f);
        float4 r;
        r.x = qone(a.x, scale, bias, sblut, crossv, centv);
        r.y = qone(a.y, scale, bias, sblut, crossv, centv);
        r.z = qone(a.z, scale, bias, sblut, crossv, centv);
        r.w = qone(a.w, scale, bias, sblut, crossv, centv);
        if (v) out[i] = r;
    }
}

// ---------------------------------------------------------------------------
extern "C" void kernel_launch(void* const* d_in, const int* in_sizes, int n_in,
                              void* d_out, int out_size)
{
    const float* x      = (const float*)d_in[0];
    const float* center = (const float*)d_in[1];
    float*       out    = (float*)d_out;
    (void)n_in; (void)out_size;

    const int n  = in_sizes[0];
    const int n4 = n >> 2;

    // opt-in to 64 KB dynamic shared memory (idempotent, capture-safe)
    cudaFuncSetAttribute(quant_fused_kernel,
                         cudaFuncAttributeMaxDynamicSharedMemorySize, LUT_SIZE);

    const int threads = 1024;
    const int blocks  = 296;   // 2 CTAs/SM x 148 SMs
    quant_fused_kernel<<<blocks, threads, LUT_SIZE>>>(
        (const float4*)x, center, (float4*)out, n4);
}